// round 9
// baseline (speedup 1.0000x reference)
#include <cuda_runtime.h>
#include <cstdint>
#include <cstddef>

// Problem constants
#define K_B   64
#define K_T   512
#define K_U   512
#define K_G3  1536
#define N_CTA 128
#define N_THR 256

// SMEM layout (bytes): weights 96KB + x tile 128KB + mbar
#define X_OFF     98304
#define X_BYTES   131072
#define MBAR_OFF  229376
#define SMEM_TOTAL 229392

// ---------------- device scratch ----------------
__device__ float g_WA[3 * K_U * 1024];            // layer0 [gate][u][k]
__device__ float g_WB[3 * K_U * 1024];            // layer1
__device__ float g_xT[(size_t)K_T * K_B * K_U];   // x blocked [t][kb][b][ki]
__device__ float g_h0[2 * K_B * K_U];             // double-buffered blocked [kb][b][ki]
__device__ float g_h1[2 * K_B * K_U];
__device__ float g_h0n[2 * K_B * K_U];            // double-buffered by t&1
__device__ float g_red[(size_t)N_CTA * 64 * 8 * 16]; // partials: [cta][b][kh][16]
__device__ unsigned g_arrive[N_CTA];
__device__ unsigned g_release;

// ---------------- init (reset per replay) ----------------
__global__ void gru_init() {
    int i = blockIdx.x * blockDim.x + threadIdx.x;
    if (i < 2 * K_B * K_U) { g_h0[i] = 0.f; g_h1[i] = 0.f; g_h0n[i] = 0.f; }
    if (i < N_CTA) g_arrive[i] = 0u;
    if (i == 0)    g_release = 0u;
}

// ---------------- weight pack: [k][3U] -> [gate][u][k] ----------------
__global__ void gru_pack_weights(const float* __restrict__ W0, const float* __restrict__ U0,
                                 const float* __restrict__ W1, const float* __restrict__ U1) {
    int idx = blockIdx.x * blockDim.x + threadIdx.x;
    if (idx >= 3 * K_U * 1024) return;
    int k = idx & 1023;
    int u = (idx >> 10) & (K_U - 1);
    int g = idx >> 19;
    int col = g * K_U + u;
    g_WA[idx] = (k < 512) ? W0[(size_t)k * K_G3 + col] : U0[(size_t)(k - 512) * K_G3 + col];
    g_WB[idx] = (k < 512) ? W1[(size_t)k * K_G3 + col] : U1[(size_t)(k - 512) * K_G3 + col];
}

// ---------------- x transpose: [b][t][d] -> [t][d/4][b][4] ----------------
__global__ void gru_transpose_x(const float* __restrict__ x) {
    size_t idx = (size_t)blockIdx.x * blockDim.x + threadIdx.x;
    if (idx >= (size_t)K_T * 128 * K_B) return;
    int b  = idx & 63;
    int kb = (int)(idx >> 6) & 127;
    int t  = (int)(idx >> 13);
    float4 v = reinterpret_cast<const float4*>(x)[((size_t)b * K_T + t) * 128 + kb];
    reinterpret_cast<float4*>(g_xT)[idx] = v;
}

// ---------------- flag-based grid barrier (1 per step) ----------------
__device__ __forceinline__ void grid_barrier(unsigned step) {
    __syncthreads();
    if (threadIdx.x == 0) {
        __threadfence();
        *(volatile unsigned*)&g_arrive[blockIdx.x] = step;
    }
    if (blockIdx.x == 0) {
        if (threadIdx.x < N_CTA)
            while (*(volatile unsigned*)&g_arrive[threadIdx.x] < step) { }
        __syncthreads();
        if (threadIdx.x == 0) {
            __threadfence();
            *(volatile unsigned*)&g_release = step;
        }
    } else {
        if (threadIdx.x == 0) {
            while (*(volatile unsigned*)&g_release < step) { }
            __threadfence();
        }
    }
    __syncthreads();
}

__device__ __forceinline__ float sigmoid_f(float x) { return 1.f / (1.f + __expf(-x)); }

// ---------------- primitives ----------------
__device__ __forceinline__ void lds2(uint32_t a, uint64_t& x, uint64_t& y) {
    asm volatile("ld.shared.v2.u64 {%0,%1},[%2];" : "=l"(x), "=l"(y) : "r"(a));
}
__device__ __forceinline__ void ldg2(const void* p, uint64_t& x, uint64_t& y) {
    asm volatile("ld.global.cg.v2.u64 {%0,%1},[%2];" : "=l"(x), "=l"(y) : "l"(p));
}
__device__ __forceinline__ void fma2(uint64_t& d, uint64_t a, uint64_t b) {
    asm volatile("fma.rn.f32x2 %0,%1,%2,%0;" : "+l"(d) : "l"(a), "l"(b));
}
__device__ __forceinline__ float redu1(uint64_t a) {
    float x0, x1;
    asm volatile("mov.b64 {%0,%1},%2;" : "=f"(x0), "=f"(x1) : "l"(a));
    return x0 + x1;
}

#define MWAIT(mbar, ph) do {                                                             \
    asm volatile("{\n\t.reg .pred P1;\n\t"                                               \
                 "WL_%=:\n\t"                                                            \
                 "mbarrier.try_wait.parity.acquire.cta.shared::cta.b64 P1,[%0],%1;\n\t" \
                 "@P1 bra.uni WD_%=;\n\t"                                                \
                 "bra.uni WL_%=;\n\t"                                                    \
                 "WD_%=:\n\t}"                                                           \
                 :: "r"(mbar), "r"(ph) : "memory");                                      \
} while (0)

// FMA body for one 4-k chunk: 2 b x 4 u x 3 gates
#define CHUNK_FMA(C)                                                                     \
    _Pragma("unroll")                                                                    \
    for (int g = 0; g < 3; ++g) {                                                        \
        _Pragma("unroll")                                                                \
        for (int u = 0; u < 4; ++u) {                                                    \
            uint64_t wl, wh;                                                             \
            lds2(wb + (unsigned)(g * 16384 + u * 4096 + (C) * 16), wl, wh);              \
            const int j = g * 4 + u;                                                     \
            fma2(acc[j], v0l, wl);      fma2(acc[j], v0h, wh);                           \
            fma2(acc[12 + j], v1l, wl); fma2(acc[12 + j], v1h, wh);                      \
        }                                                                                \
    }

// 128-k quarter-dot, v from SMEM
__device__ __forceinline__ void dotq_s(uint32_t vb, uint32_t wb, uint64_t* acc) {
#pragma unroll
    for (int c = 0; c < 32; ++c) {
        uint64_t v0l, v0h, v1l, v1h;
        lds2(vb + (unsigned)c * 1024u, v0l, v0h);
        lds2(vb + (unsigned)c * 1024u + 512u, v1l, v1h);
        CHUNK_FMA(c)
    }
}

// 128-k quarter-dot, v from global (.cg), group-of-4 double-buffered prefetch
__device__ __forceinline__ void dotq_g(const char* vp, uint32_t wb, uint64_t* acc) {
    uint64_t va[16], vn[16];
#pragma unroll
    for (int j = 0; j < 4; ++j) {
        ldg2(vp + (size_t)j * 1024, va[4 * j], va[4 * j + 1]);
        ldg2(vp + (size_t)j * 1024 + 512, va[4 * j + 2], va[4 * j + 3]);
    }
#pragma unroll
    for (int grp = 0; grp < 8; ++grp) {
        if (grp < 7) {
#pragma unroll
            for (int j = 0; j < 4; ++j) {
                ldg2(vp + (size_t)((grp + 1) * 4 + j) * 1024, vn[4 * j], vn[4 * j + 1]);
                ldg2(vp + (size_t)((grp + 1) * 4 + j) * 1024 + 512, vn[4 * j + 2], vn[4 * j + 3]);
            }
        }
#pragma unroll
        for (int c4 = 0; c4 < 4; ++c4) {
            const int c = grp * 4 + c4;
            uint64_t v0l = va[4 * c4], v0h = va[4 * c4 + 1];
            uint64_t v1l = va[4 * c4 + 2], v1h = va[4 * c4 + 3];
            CHUNK_FMA(c)
        }
#pragma unroll
        for (int j = 0; j < 16; ++j) va[j] = vn[j];
    }
}

// write 24 partial scalars (2 b x 12) to g_red[cta][b][kh][16]
__device__ __forceinline__ void write_partials(int cta, int lane, int kh, const uint64_t* acc) {
#pragma unroll
    for (int bp = 0; bp < 2; ++bp) {
        int b = lane + bp * 32;
        float4* dst = reinterpret_cast<float4*>(g_red) + ((size_t)(cta * 64 + b) * 8 + kh) * 4;
#pragma unroll
        for (int q = 0; q < 3; ++q) {
            float4 v;
            v.x = redu1(acc[bp * 12 + q * 4 + 0]);
            v.y = redu1(acc[bp * 12 + q * 4 + 1]);
            v.z = redu1(acc[bp * 12 + q * 4 + 2]);
            v.w = redu1(acc[bp * 12 + q * 4 + 3]);
            dst[q] = v;
        }
    }
}

// all-thread gather: thread (b = tid>>2, q = tid&3) -> slo/shi[12] via 6 ldcg + shfl
__device__ __forceinline__ void gather2(int cta, int b, int q, float* slo, float* shi) {
    const float4* base = reinterpret_cast<const float4*>(g_red)
                       + (size_t)(cta * 64 + b) * 32 + q * 8;
    float s[12];
#pragma unroll
    for (int i = 0; i < 3; ++i) {
        float4 a = __ldcg(base + i);
        float4 c = __ldcg(base + 4 + i);
        s[i * 4 + 0] = a.x + c.x; s[i * 4 + 1] = a.y + c.y;
        s[i * 4 + 2] = a.z + c.z; s[i * 4 + 3] = a.w + c.w;
    }
#pragma unroll
    for (int i = 0; i < 12; ++i)
        s[i] += __shfl_xor_sync(0xffffffffu, s[i], 1);
    // lanes q<2 hold slo (kh 0..3); q>=2 hold shi (kh 4..7); exchange via xor 2
#pragma unroll
    for (int i = 0; i < 12; ++i) {
        float o = __shfl_xor_sync(0xffffffffu, s[i], 2);
        slo[i] = (q < 2) ? s[i] : o;
        shi[i] = (q < 2) ? o : s[i];
    }
}
__device__ __forceinline__ float pick4(const float* a, int q) {
    float r = (q == 1) ? a[1] : a[0];
    float r2 = (q == 3) ? a[3] : a[2];
    return (q < 2) ? r : r2;
}

// ---------------- persistent GRU kernel ----------------
__global__ void __launch_bounds__(N_THR, 1) gru_main(
    const int* __restrict__ mask,
    const float* __restrict__ b0, const float* __restrict__ b1,
    float* __restrict__ out) {

    extern __shared__ char smem[];
    const uint32_t sbase = (uint32_t)__cvta_generic_to_shared(smem);
    float4* sW4 = reinterpret_cast<float4*>(smem);

    const int tid  = threadIdx.x;
    const int lane = tid & 31;
    const int kh   = tid >> 5;              // dot role: K-eighth
    const int cta  = blockIdx.x;
    const int u0g  = cta << 2;
    const int fb   = tid >> 2;              // finish role: batch
    const int fq   = tid & 3;               // finish role: u within CTA

    // ---- stage weights into SMEM ----
    for (int layer = 0; layer < 2; ++layer) {
        const float4* src = reinterpret_cast<const float4*>(layer ? g_WB : g_WA);
#pragma unroll
        for (int g = 0; g < 3; ++g)
#pragma unroll
            for (int w = 0; w < 4; ++w)
                sW4[((layer * 3 + g) * 4 + w) * 256 + tid] = src[(g * K_U + u0g + w) * 256 + tid];
    }
    const uint32_t mbar = sbase + MBAR_OFF;
    if (tid == 0)
        asm volatile("mbarrier.init.shared.b64 [%0], 1;" :: "r"(mbar));
    __syncthreads();

    // ---- prefetch x tile for t=0 ----
    if (tid == 0) {
        asm volatile("fence.proxy.async.shared::cta;");
        asm volatile("mbarrier.arrive.expect_tx.shared.b64 _,[%0],%1;" :: "r"(mbar), "r"(X_BYTES));
        asm volatile("cp.async.bulk.shared::cta.global.mbarrier::complete_tx::bytes [%0],[%1],%2,[%3];"
                     :: "r"(sbase + X_OFF), "l"((const void*)g_xT), "r"(X_BYTES), "r"(mbar) : "memory");
    }

    // weight bases for this warp's K-eighth
    const uint32_t wA = sbase + (uint32_t)(kh & 3) * 512u + ((kh & 4) ? 2048u : 0u);
    const uint32_t wB = wA + 49152u;

    // per-thread (finish role) biases for u = u0g + fq
    const int uu = u0g + fq;
    const float bAz = b0[uu] + b0[K_G3 + uu];
    const float bAr = b0[K_U + uu] + b0[K_G3 + K_U + uu];
    const float bAi = b0[2 * K_U + uu];
    const float bAh = b0[K_G3 + 2 * K_U + uu];
    const float bBz = b1[uu] + b1[K_G3 + uu];
    const float bBr = b1[K_U + uu] + b1[K_G3 + K_U + uu];
    const float bBi = b1[2 * K_U + uu];
    const float bBh = b1[K_G3 + 2 * K_U + uu];

    const int sidx = cta * 256 + fb * 4 + fq;   // blocked [kb=cta][b][ki] state index
    float h0v = 0.f, h1v = 0.f, prev = 0.f;
    bool m = false;

    for (int t = 0; t < K_T; ++t) {
        const int p = t & 1;

        // ======== phase A: layer 0, [x(smem, kh<4) ; h0(global, kh>=4)] ========
        MWAIT(mbar, (unsigned)p);
        uint64_t acc[24];
#pragma unroll
        for (int i = 0; i < 24; ++i) acc[i] = 0;
        if (kh < 4) {
            dotq_s(sbase + X_OFF + (unsigned)kh * 32768u + (unsigned)lane * 16u, wA, acc);
        } else {
            dotq_g((const char*)g_h0 + (size_t)p * 131072 + (size_t)(kh - 4) * 32768
                   + (size_t)lane * 16, wA, acc);
        }
        __syncthreads();   // x consumed; B(t-1) gather done (red reusable)
        if (tid == 0 && t + 1 < K_T) {
            asm volatile("fence.proxy.async.shared::cta;");
            asm volatile("mbarrier.arrive.expect_tx.shared.b64 _,[%0],%1;" :: "r"(mbar), "r"(X_BYTES));
            asm volatile("cp.async.bulk.shared::cta.global.mbarrier::complete_tx::bytes [%0],[%1],%2,[%3];"
                         :: "r"(sbase + X_OFF), "l"((const void*)(g_xT + (size_t)(t + 1) * 32768)),
                            "r"(X_BYTES), "r"(mbar) : "memory");
        }
        write_partials(cta, lane, kh, acc);
        __syncthreads();
        // ---- A finish (all threads; thread = (fb, fq)) ----
        {
            float slo[12], shi[12];
            gather2(cta, fb, fq, slo, shi);
            m = mask[(size_t)fb * K_T + t] != 0;
            float z    = sigmoid_f(pick4(slo, fq) + pick4(shi, fq) + bAz);
            float r    = sigmoid_f(pick4(slo + 4, fq) + pick4(shi + 4, fq) + bAr);
            float cand = tanhf(pick4(slo + 8, fq) + bAi + r * (pick4(shi + 8, fq) + bAh));
            float h0n  = z * h0v + (1.f - z) * cand;
            h0v = m ? h0n : h0v;
            g_h0n[p * 32768 + sidx] = h0n;
            g_h0[(p ^ 1) * 32768 + sidx] = h0v;
        }
        grid_barrier((unsigned)(t + 1));    // single barrier per step

        // ======== phase B: layer 1, [h0n(kh<4) ; h1(kh>=4)] ========
#pragma unroll
        for (int i = 0; i < 24; ++i) acc[i] = 0;
        if (kh < 4) {
            dotq_g((const char*)g_h0n + (size_t)p * 131072 + (size_t)kh * 32768
                   + (size_t)lane * 16, wB, acc);
        } else {
            dotq_g((const char*)g_h1 + (size_t)p * 131072 + (size_t)(kh - 4) * 32768
                   + (size_t)lane * 16, wB, acc);
        }
        write_partials(cta, lane, kh, acc);   // A-gather done pre-barrier; no extra sync needed
        __syncthreads();
        // ---- B finish ----
        {
            float slo[12], shi[12];
            gather2(cta, fb, fq, slo, shi);
            float z    = sigmoid_f(pick4(slo, fq) + pick4(shi, fq) + bBz);
            float r    = sigmoid_f(pick4(slo + 4, fq) + pick4(shi + 4, fq) + bBr);
            float cand = tanhf(pick4(slo + 8, fq) + bBi + r * (pick4(shi + 8, fq) + bBh));
            float h1n  = z * h1v + (1.f - z) * cand;
            h1v  = m ? h1n : h1v;
            prev = m ? h1n : prev;
            g_h1[(p ^ 1) * 32768 + sidx] = h1v;
            out[((size_t)fb * K_T + t) * K_U + u0g + fq] = prev;
        }
        // no barrier: A(t+1) touches nothing B(t) exchanges before next bar
    }

    // finals: (output, h0f, h1f) in d_out
    const size_t fin = (size_t)K_B * K_T * K_U;
    out[fin + (size_t)fb * K_U + u0g + fq] = h0v;
    out[fin + (size_t)K_B * K_U + (size_t)fb * K_U + u0g + fq] = h1v;
}

// ---------------- launch ----------------
extern "C" void kernel_launch(void* const* d_in, const int* in_sizes, int n_in,
                              void* d_out, int out_size) {
    (void)in_sizes; (void)n_in; (void)out_size;
    const float* x    = (const float*)d_in[0];
    const int*   mask = (const int*)d_in[1];
    const float* W0   = (const float*)d_in[2];
    const float* U0   = (const float*)d_in[3];
    const float* b0   = (const float*)d_in[4];
    const float* W1   = (const float*)d_in[5];
    const float* U1   = (const float*)d_in[6];
    const float* b1   = (const float*)d_in[7];
    float*       out  = (float*)d_out;

    cudaFuncSetAttribute(gru_main, cudaFuncAttributeMaxDynamicSharedMemorySize, SMEM_TOTAL);

    gru_init<<<(2 * K_B * K_U + 255) / 256, 256>>>();
    gru_pack_weights<<<(3 * K_U * 1024 + 255) / 256, 256>>>(W0, U0, W1, U1);
    {
        size_t n4 = (size_t)K_T * 128 * K_B;
        gru_transpose_x<<<(unsigned)((n4 + 255) / 256), 256>>>(x);
    }
    gru_main<<<N_CTA, N_THR, SMEM_TOTAL>>>(mask, b0, b1, out);
}

// round 10
// speedup vs baseline: 1.2733x; 1.2733x over previous
#include <cuda_runtime.h>
#include <cstdint>
#include <cstddef>

// Problem constants
#define K_B   64
#define K_T   512
#define K_U   512
#define K_G3  1536
#define N_CTA 128
#define N_THR 512

// SMEM layout (bytes): weights 96KB @0, partials 48KB, biases
#define RED_OFF   98304
#define BIAS_OFF  147456
#define SMEM_TOTAL 147712

// ---------------- device scratch ----------------
__device__ float g_WA[3 * K_U * 1024];            // layer0 [gate][u][k]
__device__ float g_WB[3 * K_U * 1024];            // layer1
__device__ float g_xT[(size_t)K_T * K_B * K_U];   // x blocked [t][kb][b][ki]
__device__ float g_h0[2 * K_B * K_U];             // double-buffered blocked [kb][b][ki]
__device__ float g_h1[2 * K_B * K_U];
__device__ float g_h0n[2 * K_B * K_U];            // double-buffered by t&1
__device__ unsigned g_arrive[N_CTA];
__device__ unsigned g_release;

// ---------------- init (reset per replay) ----------------
__global__ void gru_init() {
    int i = blockIdx.x * blockDim.x + threadIdx.x;
    if (i < 2 * K_B * K_U) { g_h0[i] = 0.f; g_h1[i] = 0.f; g_h0n[i] = 0.f; }
    if (i < N_CTA) g_arrive[i] = 0u;
    if (i == 0)    g_release = 0u;
}

// ---------------- weight pack: [k][3U] -> [gate][u][k] ----------------
__global__ void gru_pack_weights(const float* __restrict__ W0, const float* __restrict__ U0,
                                 const float* __restrict__ W1, const float* __restrict__ U1) {
    int idx = blockIdx.x * blockDim.x + threadIdx.x;
    if (idx >= 3 * K_U * 1024) return;
    int k = idx & 1023;
    int u = (idx >> 10) & (K_U - 1);
    int g = idx >> 19;
    int col = g * K_U + u;
    g_WA[idx] = (k < 512) ? W0[(size_t)k * K_G3 + col] : U0[(size_t)(k - 512) * K_G3 + col];
    g_WB[idx] = (k < 512) ? W1[(size_t)k * K_G3 + col] : U1[(size_t)(k - 512) * K_G3 + col];
}

// ---------------- x transpose: [b][t][d] -> [t][d/4][b][4] ----------------
__global__ void gru_transpose_x(const float* __restrict__ x) {
    size_t idx = (size_t)blockIdx.x * blockDim.x + threadIdx.x;
    if (idx >= (size_t)K_T * 128 * K_B) return;
    int b  = idx & 63;
    int kb = (int)(idx >> 6) & 127;
    int t  = (int)(idx >> 13);
    float4 v = reinterpret_cast<const float4*>(x)[((size_t)b * K_T + t) * 128 + kb];
    reinterpret_cast<float4*>(g_xT)[idx] = v;
}

// ---------------- flag-based grid barrier (1 per step) ----------------
__device__ __forceinline__ void grid_barrier(unsigned step) {
    __syncthreads();
    if (threadIdx.x == 0) {
        __threadfence();
        *(volatile unsigned*)&g_arrive[blockIdx.x] = step;
    }
    if (blockIdx.x == 0) {
        if (threadIdx.x < N_CTA)
            while (*(volatile unsigned*)&g_arrive[threadIdx.x] < step) { }
        __syncthreads();
        if (threadIdx.x == 0) {
            __threadfence();
            *(volatile unsigned*)&g_release = step;
        }
    } else {
        if (threadIdx.x == 0) {
            while (*(volatile unsigned*)&g_release < step) { }
            __threadfence();
        }
    }
    __syncthreads();
}

__device__ __forceinline__ float sigmoid_f(float x) { return 1.f / (1.f + __expf(-x)); }

// ---------------- primitives ----------------
__device__ __forceinline__ void lds2(uint32_t a, uint64_t& x, uint64_t& y) {
    asm volatile("ld.shared.v2.u64 {%0,%1},[%2];" : "=l"(x), "=l"(y) : "r"(a));
}
__device__ __forceinline__ void ldg2(const void* p, uint64_t& x, uint64_t& y) {
    asm volatile("ld.global.cg.v2.u64 {%0,%1},[%2];" : "=l"(x), "=l"(y) : "l"(p));
}
__device__ __forceinline__ void fma2(uint64_t& d, uint64_t a, uint64_t b) {
    asm volatile("fma.rn.f32x2 %0,%1,%2,%0;" : "+l"(d) : "l"(a), "l"(b));
}
__device__ __forceinline__ float redu1(uint64_t a) {
    float x0, x1;
    asm volatile("mov.b64 {%0,%1},%2;" : "=f"(x0), "=f"(x1) : "l"(a));
    return x0 + x1;
}
__device__ __forceinline__ void sts32(uint32_t a, float v) {
    asm volatile("st.shared.f32 [%0],%1;" :: "r"(a), "f"(v));
}
__device__ __forceinline__ float lds32(uint32_t a) {
    float v;
    asm volatile("ld.shared.f32 %0,[%1];" : "=f"(v) : "r"(a));
    return v;
}

// FMA body for one 4-k chunk: 2 b x 4 u x 3 gates. wb = weight base for (layer,kh)
#define CHUNK_FMA(C)                                                                     \
    _Pragma("unroll")                                                                    \
    for (int g = 0; g < 3; ++g) {                                                        \
        _Pragma("unroll")                                                                \
        for (int u = 0; u < 4; ++u) {                                                    \
            uint64_t wl, wh;                                                             \
            lds2(wb + (unsigned)(g * 16384 + u * 4096 + (C) * 16), wl, wh);              \
            const int j = g * 4 + u;                                                     \
            fma2(acc[j], v0l, wl);      fma2(acc[j], v0h, wh);                           \
            fma2(acc[12 + j], v1l, wl); fma2(acc[12 + j], v1h, wh);                      \
        }                                                                                \
    }

// 64-k dot for this warp: 16 chunks, group-of-2 double-buffered global prefetch.
// vp: base of chunk 0 for this lane (b at +0, b+32 at +512); chunk stride 1024B.
__device__ __forceinline__ void dot16(const char* vp, uint32_t wb, uint64_t* acc) {
    uint64_t va[8], vn[8];
    ldg2(vp, va[0], va[1]);           ldg2(vp + 512, va[2], va[3]);
    ldg2(vp + 1024, va[4], va[5]);    ldg2(vp + 1536, va[6], va[7]);
#pragma unroll
    for (int grp = 0; grp < 8; ++grp) {
        if (grp < 7) {
            const char* q = vp + (size_t)(grp + 1) * 2048;
            ldg2(q, vn[0], vn[1]);        ldg2(q + 512, vn[2], vn[3]);
            ldg2(q + 1024, vn[4], vn[5]); ldg2(q + 1536, vn[6], vn[7]);
        }
#pragma unroll
        for (int cc = 0; cc < 2; ++cc) {
            const int c = grp * 2 + cc;
            uint64_t v0l = va[cc * 4], v0h = va[cc * 4 + 1];
            uint64_t v1l = va[cc * 4 + 2], v1h = va[cc * 4 + 3];
            CHUNK_FMA(c)
        }
#pragma unroll
        for (int j = 0; j < 8; ++j) va[j] = vn[j];
    }
}

// write 24 partials to SMEM red[kh][j][b] (conflict-free: lanes = consecutive b)
__device__ __forceinline__ void write_partials(uint32_t rbase, int lane, int kh,
                                               const uint64_t* acc) {
#pragma unroll
    for (int bp = 0; bp < 2; ++bp) {
        const int b = lane + bp * 32;
#pragma unroll
        for (int j = 0; j < 12; ++j)
            sts32(rbase + (unsigned)(((kh * 12 + j) * 64 + b) * 4), redu1(acc[bp * 12 + j]));
    }
}

// ---------------- persistent GRU kernel ----------------
__global__ void __launch_bounds__(N_THR, 1) gru_main(
    const int* __restrict__ mask,
    const float* __restrict__ b0, const float* __restrict__ b1,
    float* __restrict__ out) {

    extern __shared__ char smem[];
    const uint32_t sbase = (uint32_t)__cvta_generic_to_shared(smem);
    float4* sW4 = reinterpret_cast<float4*>(smem);

    const int tid  = threadIdx.x;
    const int lane = tid & 31;
    const int kh   = tid >> 5;              // 0..15: K-sixteenth (64 k each)
    const int cta  = blockIdx.x;
    const int u0g  = cta << 2;

    // ---- stage weights into SMEM: [layer][gate][uu][1024] ----
    for (int idx = tid; idx < 6144; idx += N_THR) {
        int i = idx & 255;
        int w = (idx >> 8) & 3;
        int g = (idx >> 10) % 3;
        int layer = idx / 3072;
        const float4* src = reinterpret_cast<const float4*>(layer ? g_WB : g_WA);
        sW4[idx] = src[(size_t)(g * K_U + u0g + w) * 256 + i];
    }
    // ---- stage biases: sBias[layer][u][4] = {bz, br, bi, bh} ----
    if (tid < 32) {
        int layer = tid >> 4, u = (tid >> 2) & 3, q = tid & 3;
        const float* bb = layer ? b1 : b0;
        int uu = u0g + u;
        float v;
        if (q == 0)      v = bb[uu] + bb[K_G3 + uu];
        else if (q == 1) v = bb[K_U + uu] + bb[K_G3 + K_U + uu];
        else if (q == 2) v = bb[2 * K_U + uu];
        else             v = bb[K_G3 + 2 * K_U + uu];
        sts32(sbase + BIAS_OFF + (unsigned)tid * 4u, v);
    }
    __syncthreads();

    // weight base for this warp's 64 k (x-half kh<8 and h-half kh>=8 are contiguous: kh*256B)
    const uint32_t wA = sbase + (uint32_t)kh * 256u;
    const uint32_t wB = wA + 49152u;
    const uint32_t rbase = sbase + RED_OFF;

    float4 h0v = make_float4(0.f, 0.f, 0.f, 0.f);
    float4 h1v = make_float4(0.f, 0.f, 0.f, 0.f);
    float4 prevv = make_float4(0.f, 0.f, 0.f, 0.f);
    bool m = false;
    const int sidx4 = cta * 64 + tid;       // float4 state slot for finish thread (tid<64)

    for (int t = 0; t < K_T; ++t) {
        const int p = t & 1;
        uint64_t acc[24];

        // ======== phase A: layer 0, [x(kh<8) ; h0(kh>=8)] ========
#pragma unroll
        for (int i = 0; i < 24; ++i) acc[i] = 0;
        if (kh < 8) {
            dot16((const char*)g_xT + (size_t)t * 131072 + (size_t)kh * 16384
                  + (size_t)lane * 16, wA, acc);
        } else {
            dot16((const char*)g_h0 + (size_t)p * 131072 + (size_t)(kh - 8) * 16384
                  + (size_t)lane * 16, wA, acc);
        }
        __syncthreads();                     // prior finish readers done
        write_partials(rbase, lane, kh, acc);
        __syncthreads();
        // ---- A finish: 64 threads, thread = b, all 4 u ----
        if (tid < 64) {
            const int b = tid;
            float lo[12], hi[12];
#pragma unroll
            for (int j = 0; j < 12; ++j) { lo[j] = 0.f; hi[j] = 0.f; }
#pragma unroll
            for (int khh = 0; khh < 8; ++khh)
#pragma unroll
                for (int j = 0; j < 12; ++j) {
                    lo[j] += lds32(rbase + (unsigned)(((khh * 12 + j) * 64 + b) * 4));
                    hi[j] += lds32(rbase + (unsigned)((((khh + 8) * 12 + j) * 64 + b) * 4));
                }
            m = mask[(size_t)b * K_T + t] != 0;
            float4 h0n4;
#pragma unroll
            for (int u = 0; u < 4; ++u) {
                float bz = lds32(sbase + BIAS_OFF + (unsigned)((u * 4 + 0) * 4));
                float br = lds32(sbase + BIAS_OFF + (unsigned)((u * 4 + 1) * 4));
                float bi = lds32(sbase + BIAS_OFF + (unsigned)((u * 4 + 2) * 4));
                float bh = lds32(sbase + BIAS_OFF + (unsigned)((u * 4 + 3) * 4));
                float z    = sigmoid_f(lo[u] + hi[u] + bz);
                float r    = sigmoid_f(lo[4 + u] + hi[4 + u] + br);
                float cand = tanhf(lo[8 + u] + bi + r * (hi[8 + u] + bh));
                float hp   = ((float*)&h0v)[u];
                float h0n  = z * hp + (1.f - z) * cand;
                ((float*)&h0n4)[u] = h0n;
                ((float*)&h0v)[u]  = m ? h0n : hp;
            }
            reinterpret_cast<float4*>(g_h0n)[p * 8192 + sidx4] = h0n4;
            reinterpret_cast<float4*>(g_h0)[(p ^ 1) * 8192 + sidx4] = h0v;
        }
        grid_barrier((unsigned)(t + 1));     // single grid barrier per step

        // ======== phase B: layer 1, [h0n(kh<8) ; h1(kh>=8)] ========
#pragma unroll
        for (int i = 0; i < 24; ++i) acc[i] = 0;
        if (kh < 8) {
            dot16((const char*)g_h0n + (size_t)p * 131072 + (size_t)kh * 16384
                  + (size_t)lane * 16, wB, acc);
        } else {
            dot16((const char*)g_h1 + (size_t)p * 131072 + (size_t)(kh - 8) * 16384
                  + (size_t)lane * 16, wB, acc);
        }
        __syncthreads();
        write_partials(rbase, lane, kh, acc);
        __syncthreads();
        // ---- B finish ----
        if (tid < 64) {
            const int b = tid;
            float lo[12], hi[12];
#pragma unroll
            for (int j = 0; j < 12; ++j) { lo[j] = 0.f; hi[j] = 0.f; }
#pragma unroll
            for (int khh = 0; khh < 8; ++khh)
#pragma unroll
                for (int j = 0; j < 12; ++j) {
                    lo[j] += lds32(rbase + (unsigned)(((khh * 12 + j) * 64 + b) * 4));
                    hi[j] += lds32(rbase + (unsigned)((((khh + 8) * 12 + j) * 64 + b) * 4));
                }
#pragma unroll
            for (int u = 0; u < 4; ++u) {
                float bz = lds32(sbase + BIAS_OFF + (unsigned)((16 + u * 4 + 0) * 4));
                float br = lds32(sbase + BIAS_OFF + (unsigned)((16 + u * 4 + 1) * 4));
                float bi = lds32(sbase + BIAS_OFF + (unsigned)((16 + u * 4 + 2) * 4));
                float bh = lds32(sbase + BIAS_OFF + (unsigned)((16 + u * 4 + 3) * 4));
                float z    = sigmoid_f(lo[u] + hi[u] + bz);
                float r    = sigmoid_f(lo[4 + u] + hi[4 + u] + br);
                float cand = tanhf(lo[8 + u] + bi + r * (hi[8 + u] + bh));
                float hp   = ((float*)&h1v)[u];
                float h1n  = z * hp + (1.f - z) * cand;
                ((float*)&h1v)[u]   = m ? h1n : hp;
                ((float*)&prevv)[u] = m ? h1n : ((float*)&prevv)[u];
            }
            reinterpret_cast<float4*>(g_h1)[(p ^ 1) * 8192 + sidx4] = h1v;
            reinterpret_cast<float4*>(out)[((size_t)b * K_T + t) * 128 + cta] = prevv;
        }
        // no barrier here: A(t+1) reads only x and g_h0[p^1] (ordered by bar(t+1))
    }

    // finals: (output, h0f, h1f) in d_out
    if (tid < 64) {
        const size_t fin0 = (size_t)K_B * K_T * 128;   // float4 units
        reinterpret_cast<float4*>(out)[fin0 + (size_t)tid * 128 + cta] = h0v;
        reinterpret_cast<float4*>(out)[fin0 + 8192 + (size_t)tid * 128 + cta] = h1v;
    }
}

// ---------------- launch ----------------
extern "C" void kernel_launch(void* const* d_in, const int* in_sizes, int n_in,
                              void* d_out, int out_size) {
    (void)in_sizes; (void)n_in; (void)out_size;
    const float* x    = (const float*)d_in[0];
    const int*   mask = (const int*)d_in[1];
    const float* W0   = (const float*)d_in[2];
    const float* U0   = (const float*)d_in[3];
    const float* b0   = (const float*)d_in[4];
    const float* W1   = (const float*)d_in[5];
    const float* U1   = (const float*)d_in[6];
    const float* b1   = (const float*)d_in[7];
    float*       out  = (float*)d_out;

    cudaFuncSetAttribute(gru_main, cudaFuncAttributeMaxDynamicSharedMemorySize, SMEM_TOTAL);

    gru_init<<<(2 * K_B * K_U + 255) / 256, 256>>>();
    gru_pack_weights<<<(3 * K_U * 1024 + 255) / 256, 256>>>(W0, U0, W1, U1);
    {
        size_t n4 = (size_t)K_T * 128 * K_B;
        gru_transpose_x<<<(unsigned)((n4 + 255) / 256), 256>>>(x);
    }
    gru_main<<<N_CTA, N_THR, SMEM_TOTAL>>>(mask, b0, b1, out);
}

// round 11
// speedup vs baseline: 1.4785x; 1.1612x over previous
#include <cuda_runtime.h>
#include <cstdint>
#include <cstddef>

// Problem constants
#define K_B   64
#define K_T   512
#define K_U   512
#define K_G3  1536
#define N_CTA 128
#define N_THR 512

// SMEM layout (bytes): weights 96KB @0, partials 48KB, biases
#define RED_OFF   98304
#define BIAS_OFF  147456
#define SMEM_TOTAL 147712

// ---------------- device scratch ----------------
__device__ float g_WA[3 * K_U * 1024];            // layer0 [gate][u][k]
__device__ float g_WB[3 * K_U * 1024];            // layer1
__device__ float g_xT[(size_t)K_T * K_B * K_U];   // x blocked [t][kb][b][ki]
__device__ float g_h0[2 * K_B * K_U];             // double-buffered blocked [kb][b][ki]
__device__ float g_h1[2 * K_B * K_U];
__device__ float g_h0n[2 * K_B * K_U];
__device__ unsigned g_arrive[N_CTA];
__device__ unsigned g_release;

// ---------------- init (reset per replay) ----------------
__global__ void gru_init() {
    int i = blockIdx.x * blockDim.x + threadIdx.x;
    if (i < 2 * K_B * K_U) { g_h0[i] = 0.f; g_h1[i] = 0.f; g_h0n[i] = 0.f; }
    if (i < N_CTA) g_arrive[i] = 0u;
    if (i == 0)    g_release = 0u;
}

// ---------------- weight pack: [k][3U] -> [gate][u][k] ----------------
__global__ void gru_pack_weights(const float* __restrict__ W0, const float* __restrict__ U0,
                                 const float* __restrict__ W1, const float* __restrict__ U1) {
    int idx = blockIdx.x * blockDim.x + threadIdx.x;
    if (idx >= 3 * K_U * 1024) return;
    int k = idx & 1023;
    int u = (idx >> 10) & (K_U - 1);
    int g = idx >> 19;
    int col = g * K_U + u;
    g_WA[idx] = (k < 512) ? W0[(size_t)k * K_G3 + col] : U0[(size_t)(k - 512) * K_G3 + col];
    g_WB[idx] = (k < 512) ? W1[(size_t)k * K_G3 + col] : U1[(size_t)(k - 512) * K_G3 + col];
}

// ---------------- x transpose: [b][t][d] -> [t][d/4][b][4] ----------------
__global__ void gru_transpose_x(const float* __restrict__ x) {
    size_t idx = (size_t)blockIdx.x * blockDim.x + threadIdx.x;
    if (idx >= (size_t)K_T * 128 * K_B) return;
    int b  = idx & 63;
    int kb = (int)(idx >> 6) & 127;
    int t  = (int)(idx >> 13);
    float4 v = reinterpret_cast<const float4*>(x)[((size_t)b * K_T + t) * 128 + kb];
    reinterpret_cast<float4*>(g_xT)[idx] = v;
}

// ---------------- flag-based grid barrier ----------------
__device__ __forceinline__ void grid_barrier(unsigned step) {
    __syncthreads();
    if (threadIdx.x == 0) {
        __threadfence();
        *(volatile unsigned*)&g_arrive[blockIdx.x] = step;
    }
    if (blockIdx.x == 0) {
        if (threadIdx.x < N_CTA)
            while (*(volatile unsigned*)&g_arrive[threadIdx.x] < step) { }
        __syncthreads();
        if (threadIdx.x == 0) {
            __threadfence();
            *(volatile unsigned*)&g_release = step;
        }
    } else {
        if (threadIdx.x == 0) {
            while (*(volatile unsigned*)&g_release < step) { }
            __threadfence();
        }
    }
    __syncthreads();
}

__device__ __forceinline__ float sigmoid_f(float x) { return 1.f / (1.f + __expf(-x)); }

// ---------------- primitives ----------------
__device__ __forceinline__ void lds2(uint32_t a, uint64_t& x, uint64_t& y) {
    asm volatile("ld.shared.v2.u64 {%0,%1},[%2];" : "=l"(x), "=l"(y) : "r"(a));
}
__device__ __forceinline__ void ldg2(const void* p, uint64_t& x, uint64_t& y) {
    asm volatile("ld.global.cg.v2.u64 {%0,%1},[%2];" : "=l"(x), "=l"(y) : "l"(p));
}
__device__ __forceinline__ void fma2(uint64_t& d, uint64_t a, uint64_t b) {
    asm volatile("fma.rn.f32x2 %0,%1,%2,%0;" : "+l"(d) : "l"(a), "l"(b));
}
__device__ __forceinline__ float redu1(uint64_t a) {
    float x0, x1;
    asm volatile("mov.b64 {%0,%1},%2;" : "=f"(x0), "=f"(x1) : "l"(a));
    return x0 + x1;
}
__device__ __forceinline__ void sts32(uint32_t a, float v) {
    asm volatile("st.shared.f32 [%0],%1;" :: "r"(a), "f"(v));
}
__device__ __forceinline__ float lds32(uint32_t a) {
    float v;
    asm volatile("ld.shared.f32 %0,[%1];" : "=f"(v) : "r"(a));
    return v;
}

// FMA body for one 4-k chunk: 2 b x 4 u x 3 gates
#define CHUNK_FMA(C)                                                                     \
    _Pragma("unroll")                                                                    \
    for (int g = 0; g < 3; ++g) {                                                        \
        _Pragma("unroll")                                                                \
        for (int u = 0; u < 4; ++u) {                                                    \
            uint64_t wl, wh;                                                             \
            lds2(wb + (unsigned)(g * 16384 + u * 4096 + (C) * 16), wl, wh);              \
            const int j = g * 4 + u;                                                     \
            fma2(acc[j], v0l, wl);      fma2(acc[j], v0h, wh);                           \
            fma2(acc[12 + j], v1l, wl); fma2(acc[12 + j], v1h, wh);                      \
        }                                                                                \
    }

// 128-k dot for one warp: 32 chunks, group-of-2 double-buffered global prefetch.
__device__ __forceinline__ void dot32(const char* vp, uint32_t wb, uint64_t* acc) {
    uint64_t va[8], vn[8];
    ldg2(vp, va[0], va[1]);           ldg2(vp + 512, va[2], va[3]);
    ldg2(vp + 1024, va[4], va[5]);    ldg2(vp + 1536, va[6], va[7]);
#pragma unroll
    for (int grp = 0; grp < 16; ++grp) {
        if (grp < 15) {
            const char* q = vp + (size_t)(grp + 1) * 2048;
            ldg2(q, vn[0], vn[1]);        ldg2(q + 512, vn[2], vn[3]);
            ldg2(q + 1024, vn[4], vn[5]); ldg2(q + 1536, vn[6], vn[7]);
        }
#pragma unroll
        for (int cc = 0; cc < 2; ++cc) {
            const int c = grp * 2 + cc;
            uint64_t v0l = va[cc * 4], v0h = va[cc * 4 + 1];
            uint64_t v1l = va[cc * 4 + 2], v1h = va[cc * 4 + 3];
            CHUNK_FMA(c)
        }
#pragma unroll
        for (int j = 0; j < 8; ++j) va[j] = vn[j];
    }
}

// write 24 partials to SMEM red[kh][j][b]
__device__ __forceinline__ void write_partials(uint32_t rbase, int lane, int kh,
                                               const uint64_t* acc) {
#pragma unroll
    for (int bp = 0; bp < 2; ++bp) {
        const int b = lane + bp * 32;
#pragma unroll
        for (int j = 0; j < 12; ++j)
            sts32(rbase + (unsigned)(((kh * 12 + j) * 64 + b) * 4), redu1(acc[bp * 12 + j]));
    }
}

// ---------------- persistent GRU kernel (pipelined: A(r) || B(r-1) per region) ----------------
__global__ void __launch_bounds__(N_THR, 1) gru_main(
    const int* __restrict__ mask,
    const float* __restrict__ b0, const float* __restrict__ b1,
    float* __restrict__ out) {

    extern __shared__ char smem[];
    const uint32_t sbase = (uint32_t)__cvta_generic_to_shared(smem);
    float4* sW4 = reinterpret_cast<float4*>(smem);

    const int tid  = threadIdx.x;
    const int lane = tid & 31;
    const int kh   = tid >> 5;              // warp id: 0..7 = A-role, 8..15 = B-role
    const int cta  = blockIdx.x;
    const int u0g  = cta << 2;

    // ---- stage weights into SMEM: [layer][gate][uu][1024] ----
    for (int idx = tid; idx < 6144; idx += N_THR) {
        int i = idx & 255;
        int w = (idx >> 8) & 3;
        int g = (idx >> 10) % 3;
        int layer = idx / 3072;
        const float4* src = reinterpret_cast<const float4*>(layer ? g_WB : g_WA);
        sW4[idx] = src[(size_t)(g * K_U + u0g + w) * 256 + i];
    }
    // ---- stage biases: sBias[layer][u][4] = {bz, br, bi, bh} ----
    if (tid < 32) {
        int layer = tid >> 4, u = (tid >> 2) & 3, q = tid & 3;
        const float* bb = layer ? b1 : b0;
        int uu = u0g + u;
        float v;
        if (q == 0)      v = bb[uu] + bb[K_G3 + uu];
        else if (q == 1) v = bb[K_U + uu] + bb[K_G3 + K_U + uu];
        else if (q == 2) v = bb[2 * K_U + uu];
        else             v = bb[K_G3 + 2 * K_U + uu];
        sts32(sbase + BIAS_OFF + (unsigned)tid * 4u, v);
    }
    __syncthreads();

    // weight base: A warp kh covers k [kh*128, kh*128+128); B warp (kh-8) likewise in layer1
    const uint32_t wb = (kh < 8) ? (sbase + (uint32_t)kh * 512u)
                                 : (sbase + 49152u + (uint32_t)(kh - 8) * 512u);
    const uint32_t rbase = sbase + RED_OFF;

    float4 h0v = make_float4(0.f, 0.f, 0.f, 0.f);   // live in tid<64
    float4 h1v = make_float4(0.f, 0.f, 0.f, 0.f);   // live in tid 64..127
    float4 prevv = make_float4(0.f, 0.f, 0.f, 0.f);
    const int sidx4 = cta * 64;

    for (int r = 0; r <= K_T; ++r) {
        const int p = r & 1;
        uint64_t acc[24];
#pragma unroll
        for (int i = 0; i < 24; ++i) acc[i] = 0;

        // ======== dots: A(r) on warps 0-7, B(r-1) on warps 8-15 ========
        if (kh < 8) {
            if (r < K_T) {
                const char* vp = (kh < 4)
                    ? (const char*)g_xT + (size_t)r * 131072 + (size_t)kh * 32768
                      + (size_t)lane * 16
                    : (const char*)g_h0 + (size_t)p * 131072 + (size_t)(kh - 4) * 32768
                      + (size_t)lane * 16;
                dot32(vp, wb, acc);
                write_partials(rbase, lane, kh, acc);
            }
        } else {
            if (r >= 1) {
                const int pb = p ^ 1;           // (r-1)&1
                const int kb = kh - 8;
                const char* vp = (kb < 4)
                    ? (const char*)g_h0n + (size_t)pb * 131072 + (size_t)kb * 32768
                      + (size_t)lane * 16
                    : (const char*)g_h1 + (size_t)pb * 131072 + (size_t)(kb - 4) * 32768
                      + (size_t)lane * 16;
                dot32(vp, wb, acc);
                write_partials(rbase, lane, kh, acc);
            }
        }
        __syncthreads();

        // ======== merged finish: A-fin(r) on tid<64, B-fin(r-1) on tid 64..127 ========
        if (tid < 64) {
            if (r < K_T) {
                const int b = tid;
                float lo[12], hi[12];
#pragma unroll
                for (int j = 0; j < 12; ++j) { lo[j] = 0.f; hi[j] = 0.f; }
#pragma unroll
                for (int kk = 0; kk < 4; ++kk)
#pragma unroll
                    for (int j = 0; j < 12; ++j) {
                        lo[j] += lds32(rbase + (unsigned)(((kk * 12 + j) * 64 + b) * 4));
                        hi[j] += lds32(rbase + (unsigned)((((kk + 4) * 12 + j) * 64 + b) * 4));
                    }
                const bool m = mask[(size_t)b * K_T + r] != 0;
                float4 h0n4;
#pragma unroll
                for (int u = 0; u < 4; ++u) {
                    float bz = lds32(sbase + BIAS_OFF + (unsigned)((u * 4 + 0) * 4));
                    float br = lds32(sbase + BIAS_OFF + (unsigned)((u * 4 + 1) * 4));
                    float bi = lds32(sbase + BIAS_OFF + (unsigned)((u * 4 + 2) * 4));
                    float bh = lds32(sbase + BIAS_OFF + (unsigned)((u * 4 + 3) * 4));
                    float z    = sigmoid_f(lo[u] + hi[u] + bz);
                    float rr   = sigmoid_f(lo[4 + u] + hi[4 + u] + br);
                    float cand = tanhf(lo[8 + u] + bi + rr * (hi[8 + u] + bh));
                    float hp   = ((float*)&h0v)[u];
                    float h0n  = z * hp + (1.f - z) * cand;
                    ((float*)&h0n4)[u] = h0n;
                    ((float*)&h0v)[u]  = m ? h0n : hp;
                }
                reinterpret_cast<float4*>(g_h0n)[p * 8192 + sidx4 + b] = h0n4;
                reinterpret_cast<float4*>(g_h0)[(p ^ 1) * 8192 + sidx4 + b] = h0v;
            }
        } else if (tid < 128) {
            if (r >= 1) {
                const int b = tid - 64;
                float lo[12], hi[12];
#pragma unroll
                for (int j = 0; j < 12; ++j) { lo[j] = 0.f; hi[j] = 0.f; }
#pragma unroll
                for (int kk = 0; kk < 4; ++kk)
#pragma unroll
                    for (int j = 0; j < 12; ++j) {
                        lo[j] += lds32(rbase + (unsigned)((((kk + 8) * 12 + j) * 64 + b) * 4));
                        hi[j] += lds32(rbase + (unsigned)((((kk + 12) * 12 + j) * 64 + b) * 4));
                    }
                const bool m = mask[(size_t)b * K_T + (r - 1)] != 0;
#pragma unroll
                for (int u = 0; u < 4; ++u) {
                    float bz = lds32(sbase + BIAS_OFF + (unsigned)((16 + u * 4 + 0) * 4));
                    float br = lds32(sbase + BIAS_OFF + (unsigned)((16 + u * 4 + 1) * 4));
                    float bi = lds32(sbase + BIAS_OFF + (unsigned)((16 + u * 4 + 2) * 4));
                    float bh = lds32(sbase + BIAS_OFF + (unsigned)((16 + u * 4 + 3) * 4));
                    float z    = sigmoid_f(lo[u] + hi[u] + bz);
                    float rr   = sigmoid_f(lo[4 + u] + hi[4 + u] + br);
                    float cand = tanhf(lo[8 + u] + bi + rr * (hi[8 + u] + bh));
                    float hp   = ((float*)&h1v)[u];
                    float h1n  = z * hp + (1.f - z) * cand;
                    ((float*)&h1v)[u]   = m ? h1n : hp;
                    ((float*)&prevv)[u] = m ? h1n : ((float*)&prevv)[u];
                }
                // B-fin(r-1) writes h1 to buffer ((r-1)&1)^1 = p
                reinterpret_cast<float4*>(g_h1)[p * 8192 + sidx4 + b] = h1v;
                reinterpret_cast<float4*>(out)[((size_t)b * K_T + (r - 1)) * 128 + cta] = prevv;
            }
        }

        if (r < K_T) grid_barrier((unsigned)(r + 1));
    }

    // finals: (output, h0f, h1f) in d_out
    const size_t fin0 = (size_t)K_B * K_T * 128;   // float4 units
    if (tid < 64)
        reinterpret_cast<float4*>(out)[fin0 + (size_t)tid * 128 + cta] = h0v;
    else if (tid < 128)
        reinterpret_cast<float4*>(out)[fin0 + 8192 + (size_t)(tid - 64) * 128 + cta] = h1v;
}

// ---------------- launch ----------------
extern "C" void kernel_launch(void* const* d_in, const int* in_sizes, int n_in,
                              void* d_out, int out_size) {
    (void)in_sizes; (void)n_in; (void)out_size;
    const float* x    = (const float*)d_in[0];
    const int*   mask = (const int*)d_in[1];
    const float* W0   = (const float*)d_in[2];
    const float* U0   = (const float*)d_in[3];
    const float* b0   = (const float*)d_in[4];
    const float* W1   = (const float*)d_in[5];
    const float* U1   = (const float*)d_in[6];
    const float* b1   = (const float*)d_in[7];
    float*       out  = (float*)d_out;

    cudaFuncSetAttribute(gru_main, cudaFuncAttributeMaxDynamicSharedMemorySize, SMEM_TOTAL);

    gru_init<<<(2 * K_B * K_U + 255) / 256, 256>>>();
    gru_pack_weights<<<(3 * K_U * 1024 + 255) / 256, 256>>>(W0, U0, W1, U1);
    {
        size_t n4 = (size_t)K_T * 128 * K_B;
        gru_transpose_x<<<(unsigned)((n4 + 255) / 256), 256>>>(x);
    }
    gru_main<<<N_CTA, N_THR, SMEM_TOTAL>>>(mask, b0, b1, out);
}